// round 10
// baseline (speedup 1.0000x reference)
#include <cuda_runtime.h>
#include <cstdint>

// Problem dims (fixed by the dataset)
#define B_   4096
#define Qd   256
#define Dd   512
#define Hd   1024
#define Od   512
#define Ed   16
#define Kk   4
#define TM   32      // tokens per block

// ---- dynamic smem layout (float offsets) ----------------------------------
// XS : x tile, m-major [32][520], tf32, paired-k perm + xor swizzle
// W1P: W1 panel transposed n-major [128 n][72 k']   (64 k per stage)
// HCH: h chunk  m-major [32][136]  (128 local k per h-chunk)
// W2P: W2 panel transposed n-major [128 n][136 k']  (128 k per stage)
#define XS     0
#define XS_S   520
#define W1P    (XS + TM*XS_S)          // 16640
#define W1P_S  72
#define HCH    (W1P + 128*W1P_S)       // 25856
#define HCH_S  136
#define W2P    (HCH + TM*HCH_S)        // 30208
#define W2P_S  136
#define LG     (W2P + 128*W2P_S)       // 47616
#define GSM    (LG + TM*17)            // 48160
#define SMEM_F (GSM + TM*17)           // 48704 floats = 194816 bytes

// ---- helpers --------------------------------------------------------------
__device__ __forceinline__ float rna(float x){
    uint32_t u; asm("cvt.rna.tf32.f32 %0, %1;" : "=r"(u) : "f"(x));
    return __uint_as_float(u);
}
// paired-k permutation: within each 8-group, col j stored at 2*(j&3) + (j>>2)
// => (j, j+4) land adjacent -> one float2 load per tf32 fragment pair.
__device__ __forceinline__ int pkm(int k){ return (k & ~7) + 2*(k & 3) + ((k >> 2) & 1); }
// xor swizzle per row: makes frag loads AND transposed staging stores conflict-free
__device__ __forceinline__ int swz(int r){ return 2 * ((r >> 2) & 7); }

__device__ __forceinline__ void mma_tf32(float* c,
    uint32_t a0, uint32_t a1, uint32_t a2, uint32_t a3, uint32_t b0, uint32_t b1){
    asm volatile(
        "mma.sync.aligned.m16n8k8.row.col.f32.tf32.tf32.f32 "
        "{%0,%1,%2,%3}, {%4,%5,%6,%7}, {%8,%9}, {%0,%1,%2,%3};\n"
        : "+f"(c[0]), "+f"(c[1]), "+f"(c[2]), "+f"(c[3])
        : "r"(a0), "r"(a1), "r"(a2), "r"(a3), "r"(b0), "r"(b1));
}

// top-4 + softmax, ties -> lowest index (matches jax top_k)
__device__ __forceinline__ void top4_softmax(const float* v, int* idx, float* w){
    unsigned used = 0; float val[Kk];
    #pragma unroll
    for (int j = 0; j < Kk; j++){
        float best = -3.4e38f; int bi = 0;
        #pragma unroll
        for (int i = 0; i < Ed; i++)
            if (!((used >> i) & 1) && v[i] > best){ best = v[i]; bi = i; }
        used |= 1u << bi; idx[j] = bi; val[j] = best;
    }
    float m = val[0], s = 0.f;
    #pragma unroll
    for (int j = 0; j < Kk; j++){ w[j] = expf(val[j] - m); s += w[j]; }
    float inv = 1.f / s;
    #pragma unroll
    for (int j = 0; j < Kk; j++) w[j] *= inv;
}

// ======================= monolithic dense MoE (tf32 mma) ===================
__global__ __launch_bounds__(256, 1)
void moe_dense_mma(const float* __restrict__ x, const float* __restrict__ query,
                   const float* __restrict__ c8a, const float* __restrict__ c8b,
                   const float* __restrict__ tg,
                   const float* __restrict__ W1, const float* __restrict__ b1,
                   const float* __restrict__ W2, float* __restrict__ out)
{
    extern __shared__ float sm[];
    const int t  = threadIdx.x;
    const int m0 = blockIdx.x * TM;

    // --- resolve the 8192-element collision: b2 is the all-zero buffer ---
    __shared__ int s_nz[8]; __shared__ int s_zeroA;
    {
        int nz = 0;
        for (int i = t; i < Dd * Ed; i += 256) nz |= (__float_as_uint(c8a[i]) != 0u);
        #pragma unroll
        for (int s = 16; s; s >>= 1) nz |= __shfl_xor_sync(0xffffffffu, nz, s);
        if ((t & 31) == 0) s_nz[t >> 5] = nz;
        __syncthreads();
        if (t == 0){
            int v = 0;
            #pragma unroll
            for (int wp = 0; wp < 8; wp++) v |= s_nz[wp];
            s_zeroA = !v;
        }
        __syncthreads();
    }
    const float* wg = s_zeroA ? c8b : c8a;
    const float* b2 = s_zeroA ? c8a : c8b;

    // --- stage x tile: tf32-rounded, perm+swizzled (coalesced LDG) ---
    for (int p = 0; p < 64; p++){
        int idx = p * 256 + t;             // 0..16383
        int row = idx >> 9, col = idx & 511;
        sm[XS + row * XS_S + (pkm(col) ^ swz(row))] =
            rna(x[(size_t)(m0 + row) * Dd + col]);
    }

    // --- gating on EXACT fp32 x (global): logits 32 tok x 16 e ---
    #pragma unroll
    for (int rep = 0; rep < 2; rep++){
        int idx = t + rep * 256;
        int tok = idx >> 4, e = idx & 15;
        const float* xr = x + (size_t)(m0 + tok) * Dd;
        float s = 0.f;
        for (int d = 0; d < Dd; d++)  s = fmaf(xr[d], wg[d * Ed + e], s);
        const float* qr = query + (size_t)(m0 + tok) * Qd;
        for (int qd = 0; qd < Qd; qd++) s = fmaf(qr[qd], tg[qd * Ed + e], s);
        sm[LG + tok * 17 + e] = s;
    }
    __syncthreads();
    if (t < TM){
        float v[Ed];
        #pragma unroll
        for (int e = 0; e < Ed; e++) v[e] = sm[LG + t * 17 + e];
        int idx[Kk]; float w[Kk];
        top4_softmax(v, idx, w);
        float row[Ed];
        #pragma unroll
        for (int e = 0; e < Ed; e++) row[e] = 0.f;
        #pragma unroll
        for (int j = 0; j < Kk; j++) row[idx[j]] = w[j];
        #pragma unroll
        for (int e = 0; e < Ed; e++) sm[GSM + t * 17 + e] = row[e];
    }
    __syncthreads();

    // --- warp/lane decomposition (both GEMMs: 2 m-halves x 4 n-quarters) ---
    const int lane = t & 31, warp = t >> 5;
    const int gid = lane >> 2, tig = lane & 3;
    const int mh = warp & 1, nq = warp >> 1;
    const int row0 = mh * 16 + gid, row1 = row0 + 8;
    const int sw0 = swz(row0), sw1 = swz(row1);
    const int nl = t & 127, kg = t >> 7;      // staging coords
    const int snl = swz(nl);

    float yfrag[4][4][4];
    #pragma unroll
    for (int a = 0; a < 4; a++)
        #pragma unroll
        for (int b = 0; b < 4; b++)
            #pragma unroll
            for (int c = 0; c < 4; c++) yfrag[a][b][c] = 0.f;

    for (int e = 0; e < Ed; e++){
        const float* W1e = W1 + (size_t)e * Dd * Hd;
        const float* W2e = W2 + (size_t)e * Hd * Od;
        const float g0 = sm[GSM + row0 * 17 + e];
        const float g1 = sm[GSM + row1 * 17 + e];

        for (int hc = 0; hc < Hd / 128; hc++){
            // ---------------- GEMM1: h-chunk [32 x 128] over K=512 ----------
            float hf[4][4];
            #pragma unroll
            for (int a = 0; a < 4; a++)
                #pragma unroll
                for (int c = 0; c < 4; c++) hf[a][c] = 0.f;

            for (int kt = 0; kt < 8; kt++){
                __syncthreads();
                {   // stage W1 panel transposed: W1P[n][k'] (k local 0..63)
                    const float* src = W1e + (size_t)(kt*64 + kg*32) * Hd + hc*128 + nl;
                    float* dst = &sm[W1P + nl * W1P_S];
                    #pragma unroll 8
                    for (int i = 0; i < 32; i++)
                        dst[pkm(kg*32 + i) ^ snl] = rna(src[(size_t)i * Hd]);
                }
                __syncthreads();
                #pragma unroll
                for (int ks = 0; ks < 8; ks++){
                    const int k0 = kt*64 + ks*8;                 // global k (mult of 8)
                    float2 aA = *(const float2*)&sm[XS + row0*XS_S + ((k0 + 2*tig) ^ sw0)];
                    float2 aB = *(const float2*)&sm[XS + row1*XS_S + ((k0 + 2*tig) ^ sw1)];
                    uint32_t a0 = __float_as_uint(aA.x), a1 = __float_as_uint(aB.x);
                    uint32_t a2 = __float_as_uint(aA.y), a3 = __float_as_uint(aB.y);
                    const int kl = ks*8 + 2*tig;                 // panel-local
                    #pragma unroll
                    for (int nt = 0; nt < 4; nt++){
                        int n = nq*32 + nt*8 + gid;
                        float2 bb = *(const float2*)&sm[W1P + n*W1P_S + (kl ^ swz(n))];
                        mma_tf32(hf[nt], a0, a1, a2, a3,
                                 __float_as_uint(bb.x), __float_as_uint(bb.y));
                    }
                }
            }
            // store h chunk: gate * relu(h + b1), tf32-rounded (perm+swizzle)
            // (prev GEMM2 readers of HCH are past: kt-loop syncs guarantee it)
            #pragma unroll
            for (int nt = 0; nt < 4; nt++){
                int j0 = nq*32 + nt*8 + 2*tig;                   // local col, even
                float bv0 = b1[(size_t)e * Hd + hc*128 + j0];
                float bv1 = b1[(size_t)e * Hd + hc*128 + j0 + 1];
                sm[HCH + row0*HCH_S + (pkm(j0)     ^ sw0)] = rna(g0 * fmaxf(hf[nt][0] + bv0, 0.f));
                sm[HCH + row0*HCH_S + (pkm(j0 + 1) ^ sw0)] = rna(g0 * fmaxf(hf[nt][1] + bv1, 0.f));
                sm[HCH + row1*HCH_S + (pkm(j0)     ^ sw1)] = rna(g1 * fmaxf(hf[nt][2] + bv0, 0.f));
                sm[HCH + row1*HCH_S + (pkm(j0 + 1) ^ sw1)] = rna(g1 * fmaxf(hf[nt][3] + bv1, 0.f));
            }

            // ---------------- GEMM2: y += hchunk @ W2[hc rows] --------------
            #pragma unroll 1
            for (int nc = 0; nc < 4; nc++){
                __syncthreads();
                {   // stage W2 panel transposed: W2P[n][k'] (k local 0..127)
                    const float* src = W2e + (size_t)(hc*128 + kg*64) * Od + nc*128 + nl;
                    float* dst = &sm[W2P + nl * W2P_S];
                    #pragma unroll 8
                    for (int i = 0; i < 64; i++)
                        dst[pkm(kg*64 + i) ^ snl] = rna(src[(size_t)i * Od]);
                }
                __syncthreads();
                #pragma unroll
                for (int ks = 0; ks < 16; ks++){
                    const int kl = ks*8 + 2*tig;
                    float2 aA = *(const float2*)&sm[HCH + row0*HCH_S + (kl ^ sw0)];
                    float2 aB = *(const float2*)&sm[HCH + row1*HCH_S + (kl ^ sw1)];
                    uint32_t a0 = __float_as_uint(aA.x), a1 = __float_as_uint(aB.x);
                    uint32_t a2 = __float_as_uint(aA.y), a3 = __float_as_uint(aB.y);
                    #pragma unroll
                    for (int nt = 0; nt < 4; nt++){
                        int n = nq*32 + nt*8 + gid;
                        float2 bb = *(const float2*)&sm[W2P + n*W2P_S + (kl ^ swz(n))];
                        mma_tf32(yfrag[nc][nt], a0, a1, a2, a3,
                                 __float_as_uint(bb.x), __float_as_uint(bb.y));
                    }
                }
            }
        }
    }

    // --- epilogue: y + gate-weighted b2 ---
    #pragma unroll
    for (int nc = 0; nc < 4; nc++){
        #pragma unroll
        for (int nt = 0; nt < 4; nt++){
            int col = nc*128 + nq*32 + nt*8 + 2*tig;
            float s00 = 0.f, s01 = 0.f, s10 = 0.f, s11 = 0.f;
            #pragma unroll
            for (int e = 0; e < Ed; e++){
                float be0 = b2[(size_t)e * Od + col];
                float be1 = b2[(size_t)e * Od + col + 1];
                float ga = sm[GSM + row0 * 17 + e];
                float gb = sm[GSM + row1 * 17 + e];
                s00 = fmaf(ga, be0, s00); s01 = fmaf(ga, be1, s01);
                s10 = fmaf(gb, be0, s10); s11 = fmaf(gb, be1, s11);
            }
            *(float2*)&out[(size_t)(m0 + row0) * Od + col] =
                make_float2(yfrag[nc][nt][0] + s00, yfrag[nc][nt][1] + s01);
            *(float2*)&out[(size_t)(m0 + row1) * Od + col] =
                make_float2(yfrag[nc][nt][2] + s10, yfrag[nc][nt][3] + s11);
        }
    }
}

// ======================= independent loss kernel (round-9 verbatim) ========
__global__ __launch_bounds__(256, 1)
void loss_kernel(const float* __restrict__ x, const float* __restrict__ query,
                 const float* __restrict__ c8a, const float* __restrict__ c8b,
                 const float* __restrict__ tg, float* __restrict__ out, int out_size)
{
    __shared__ float red[256]; __shared__ int redi[256];
    __shared__ int s_nz[8]; __shared__ int s_zeroA;
    __shared__ float s_imp[Ed], s_cnt[Ed];
    const int t = threadIdx.x;
    {
        int nz = 0;
        for (int i = t; i < Dd * Ed; i += 256) nz |= (__float_as_uint(c8a[i]) != 0u);
        #pragma unroll
        for (int s = 16; s; s >>= 1) nz |= __shfl_xor_sync(0xffffffffu, nz, s);
        if ((t & 31) == 0) s_nz[t >> 5] = nz;
        __syncthreads();
        if (t == 0){
            int v = 0;
            #pragma unroll
            for (int wp = 0; wp < 8; wp++) v |= s_nz[wp];
            s_zeroA = !v;
        }
        __syncthreads();
    }
    const float* wg = s_zeroA ? c8b : c8a;

    float imp[Ed]; int cnt[Ed];
    #pragma unroll
    for (int e = 0; e < Ed; e++){ imp[e] = 0.f; cnt[e] = 0; }

    for (int bb = t; bb < B_; bb += 256){
        const float* xr = x + (size_t)bb * Dd;
        const float* qr = query + (size_t)bb * Qd;
        float lg[Ed];
        #pragma unroll
        for (int e = 0; e < Ed; e++) lg[e] = 0.f;
        for (int d = 0; d < Dd; d++){
            float xv = xr[d];
            const float4* w4 = (const float4*)(wg + (size_t)d * Ed);
            float4 w0 = w4[0], w1 = w4[1], w2 = w4[2], w3 = w4[3];
            lg[0]  = fmaf(xv, w0.x, lg[0]);  lg[1]  = fmaf(xv, w0.y, lg[1]);
            lg[2]  = fmaf(xv, w0.z, lg[2]);  lg[3]  = fmaf(xv, w0.w, lg[3]);
            lg[4]  = fmaf(xv, w1.x, lg[4]);  lg[5]  = fmaf(xv, w1.y, lg[5]);
            lg[6]  = fmaf(xv, w1.z, lg[6]);  lg[7]  = fmaf(xv, w1.w, lg[7]);
            lg[8]  = fmaf(xv, w2.x, lg[8]);  lg[9]  = fmaf(xv, w2.y, lg[9]);
            lg[10] = fmaf(xv, w2.z, lg[10]); lg[11] = fmaf(xv, w2.w, lg[11]);
            lg[12] = fmaf(xv, w3.x, lg[12]); lg[13] = fmaf(xv, w3.y, lg[13]);
            lg[14] = fmaf(xv, w3.z, lg[14]); lg[15] = fmaf(xv, w3.w, lg[15]);
        }
        for (int qd = 0; qd < Qd; qd++){
            float qv = qr[qd];
            const float4* w4 = (const float4*)(tg + (size_t)qd * Ed);
            float4 w0 = w4[0], w1 = w4[1], w2 = w4[2], w3 = w4[3];
            lg[0]  = fmaf(qv, w0.x, lg[0]);  lg[1]  = fmaf(qv, w0.y, lg[1]);
            lg[2]  = fmaf(qv, w0.z, lg[2]);  lg[3]  = fmaf(qv, w0.w, lg[3]);
            lg[4]  = fmaf(qv, w1.x, lg[4]);  lg[5]  = fmaf(qv, w1.y, lg[5]);
            lg[6]  = fmaf(qv, w1.z, lg[6]);  lg[7]  = fmaf(qv, w1.w, lg[7]);
            lg[8]  = fmaf(qv, w2.x, lg[8]);  lg[9]  = fmaf(qv, w2.y, lg[9]);
            lg[10] = fmaf(qv, w2.z, lg[10]); lg[11] = fmaf(qv, w2.w, lg[11]);
            lg[12] = fmaf(qv, w3.x, lg[12]); lg[13] = fmaf(qv, w3.y, lg[13]);
            lg[14] = fmaf(qv, w3.z, lg[14]); lg[15] = fmaf(qv, w3.w, lg[15]);
        }
        int idx[Kk]; float w[Kk];
        top4_softmax(lg, idx, w);
        #pragma unroll
        for (int j = 0; j < Kk; j++){ imp[idx[j]] += w[j]; cnt[idx[j]]++; }
    }

    for (int e = 0; e < Ed; e++){
        red[t] = imp[e]; redi[t] = cnt[e]; __syncthreads();
        for (int s = 128; s; s >>= 1){
            if (t < s){ red[t] += red[t + s]; redi[t] += redi[t + s]; }
            __syncthreads();
        }
        if (t == 0){ s_imp[e] = red[0]; s_cnt[e] = (float)redi[0]; }
        __syncthreads();
    }
    if (t == 0){
        float mi = 0.f, ml = 0.f;
        #pragma unroll
        for (int e = 0; e < Ed; e++){ mi += s_imp[e]; ml += s_cnt[e]; }
        mi *= (1.f / Ed); ml *= (1.f / Ed);
        float vi = 0.f, vl = 0.f;
        #pragma unroll
        for (int e = 0; e < Ed; e++){
            float di = s_imp[e] - mi; vi += di * di;
            float dl = s_cnt[e] - ml; vl += dl * dl;
        }
        vi *= (1.f / (Ed - 1)); vl *= (1.f / (Ed - 1));
        float L = 0.01f * (vi / (mi * mi + 1e-10f) + vl / (ml * ml + 1e-10f));
        for (int i = B_ * Od; i < out_size; i++) out[i] = L;
    }
}

// ---------------- launch ----------------
extern "C" void kernel_launch(void* const* d_in, const int* in_sizes, int n_in,
                              void* d_out, int out_size)
{
    // Bind inputs by element count (validated in round 9).
    int iq = -1, ix = -1, itg = -1, ib1 = -1, iW1 = -1, iW2 = -1, i81 = -1, i82 = -1;
    for (int i = 0; i < n_in; i++){
        switch (in_sizes[i]){
            case 1048576: if (iq  < 0) iq  = i; break;
            case 2097152: if (ix  < 0) ix  = i; break;
            case 4096:    if (itg < 0) itg = i; break;
            case 16384:   if (ib1 < 0) ib1 = i; break;
            case 8192:    if (i81 < 0) i81 = i; else if (i82 < 0) i82 = i; break;
            case 8388608: if (iW1 < 0) iW1 = i; else if (iW2 < 0) iW2 = i; break;
            default: break;   // k scalar etc: ignore
        }
    }
    if (iq < 0 || ix < 0 || itg < 0 || ib1 < 0 ||
        iW1 < 0 || iW2 < 0 || i81 < 0 || i82 < 0){
        iq = 0; ix = 1; i81 = 2; itg = 3; iW1 = 4; ib1 = 5; iW2 = 6; i82 = 7;
    }
    const float* query = (const float*)d_in[iq];
    const float* x     = (const float*)d_in[ix];
    const float* c8a   = (const float*)d_in[i81];
    const float* c8b   = (const float*)d_in[i82];
    const float* tg    = (const float*)d_in[itg];
    const float* W1    = (const float*)d_in[iW1];
    const float* b1    = (const float*)d_in[ib1];
    const float* W2    = (const float*)d_in[iW2];
    float* out = (float*)d_out;

    const int smem_bytes = SMEM_F * 4;   // 194816
    cudaFuncSetAttribute(moe_dense_mma,
                         cudaFuncAttributeMaxDynamicSharedMemorySize, smem_bytes);

    moe_dense_mma<<<B_ / TM, 256, smem_bytes>>>(x, query, c8a, c8b, tg, W1, b1, W2, out);
    if (out_size > B_ * Od)
        loss_kernel<<<1, 256>>>(x, query, c8a, c8b, tg, out, out_size);
}

// round 11
// speedup vs baseline: 1.2889x; 1.2889x over previous
#include <cuda_runtime.h>
#include <cstdint>

// Problem dims (fixed by the dataset)
#define B_   4096
#define Qd   256
#define Dd   512
#define Hd   1024
#define Od   512
#define Ed   16
#define Kk   4
#define TM   32      // tokens per block
#define NT_  512     // threads per block (16 warps, 4 per SMSP)

// ---- dynamic smem layout (float offsets) — identical to round 10 ----------
#define XS     0
#define XS_S   520
#define W1P    (XS + TM*XS_S)          // 16640
#define W1P_S  72
#define HCH    (W1P + 128*W1P_S)       // 25856
#define HCH_S  136
#define W2P    (HCH + TM*HCH_S)        // 30208
#define W2P_S  136
#define LG     (W2P + 128*W2P_S)       // 47616
#define GSM    (LG + TM*17)            // 48160
#define SMEM_F (GSM + TM*17)           // 48704 floats = 194816 bytes

// ---- helpers --------------------------------------------------------------
__device__ __forceinline__ float rna(float x){
    uint32_t u; asm("cvt.rna.tf32.f32 %0, %1;" : "=r"(u) : "f"(x));
    return __uint_as_float(u);
}
// paired-k permutation: (j, j+4) adjacent -> one float2 per tf32 frag pair
__device__ __forceinline__ int pkm(int k){ return (k & ~7) + 2*(k & 3) + ((k >> 2) & 1); }
// xor swizzle per row: frag loads AND transposed staging stores conflict-free
__device__ __forceinline__ int swz(int r){ return 2 * ((r >> 2) & 7); }

__device__ __forceinline__ void mma_tf32(float* c,
    uint32_t a0, uint32_t a1, uint32_t a2, uint32_t a3, uint32_t b0, uint32_t b1){
    asm volatile(
        "mma.sync.aligned.m16n8k8.row.col.f32.tf32.tf32.f32 "
        "{%0,%1,%2,%3}, {%4,%5,%6,%7}, {%8,%9}, {%0,%1,%2,%3};\n"
        : "+f"(c[0]), "+f"(c[1]), "+f"(c[2]), "+f"(c[3])
        : "r"(a0), "r"(a1), "r"(a2), "r"(a3), "r"(b0), "r"(b1));
}

// top-4 + softmax, ties -> lowest index (matches jax top_k)
__device__ __forceinline__ void top4_softmax(const float* v, int* idx, float* w){
    unsigned used = 0; float val[Kk];
    #pragma unroll
    for (int j = 0; j < Kk; j++){
        float best = -3.4e38f; int bi = 0;
        #pragma unroll
        for (int i = 0; i < Ed; i++)
            if (!((used >> i) & 1) && v[i] > best){ best = v[i]; bi = i; }
        used |= 1u << bi; idx[j] = bi; val[j] = best;
    }
    float m = val[0], s = 0.f;
    #pragma unroll
    for (int j = 0; j < Kk; j++){ w[j] = expf(val[j] - m); s += w[j]; }
    float inv = 1.f / s;
    #pragma unroll
    for (int j = 0; j < Kk; j++) w[j] *= inv;
}

// ======================= monolithic dense MoE (tf32 mma, 16 warps) =========
__global__ __launch_bounds__(NT_, 1)
void moe_dense_mma(const float* __restrict__ x, const float* __restrict__ query,
                   const float* __restrict__ c8a, const float* __restrict__ c8b,
                   const float* __restrict__ tg,
                   const float* __restrict__ W1, const float* __restrict__ b1,
                   const float* __restrict__ W2, float* __restrict__ out)
{
    extern __shared__ float sm[];
    const int t  = threadIdx.x;
    const int m0 = blockIdx.x * TM;

    // --- resolve the 8192-element collision: b2 is the all-zero buffer ---
    __shared__ int s_nz[16]; __shared__ int s_zeroA;
    {
        int nz = 0;
        for (int i = t; i < Dd * Ed; i += NT_) nz |= (__float_as_uint(c8a[i]) != 0u);
        #pragma unroll
        for (int s = 16; s; s >>= 1) nz |= __shfl_xor_sync(0xffffffffu, nz, s);
        if ((t & 31) == 0) s_nz[t >> 5] = nz;
        __syncthreads();
        if (t == 0){
            int v = 0;
            #pragma unroll
            for (int wp = 0; wp < 16; wp++) v |= s_nz[wp];
            s_zeroA = !v;
        }
        __syncthreads();
    }
    const float* wg = s_zeroA ? c8b : c8a;
    const float* b2 = s_zeroA ? c8a : c8b;

    // --- stage x tile: tf32-rounded, perm+swizzled (coalesced LDG) ---
    for (int p = 0; p < 32; p++){
        int idx = p * NT_ + t;             // 0..16383
        int row = idx >> 9, col = idx & 511;
        sm[XS + row * XS_S + (pkm(col) ^ swz(row))] =
            rna(x[(size_t)(m0 + row) * Dd + col]);
    }

    // --- gating on EXACT fp32 x (global): one (tok, e) logit per thread ---
    {
        int tok = t >> 4, e = t & 15;      // 512 threads = 32 x 16
        const float* xr = x + (size_t)(m0 + tok) * Dd;
        float s = 0.f;
        for (int d = 0; d < Dd; d++)  s = fmaf(xr[d], wg[d * Ed + e], s);
        const float* qr = query + (size_t)(m0 + tok) * Qd;
        for (int qd = 0; qd < Qd; qd++) s = fmaf(qr[qd], tg[qd * Ed + e], s);
        sm[LG + tok * 17 + e] = s;
    }
    __syncthreads();
    if (t < TM){
        float v[Ed];
        #pragma unroll
        for (int e = 0; e < Ed; e++) v[e] = sm[LG + t * 17 + e];
        int idx[Kk]; float w[Kk];
        top4_softmax(v, idx, w);
        float row[Ed];
        #pragma unroll
        for (int e = 0; e < Ed; e++) row[e] = 0.f;
        #pragma unroll
        for (int j = 0; j < Kk; j++) row[idx[j]] = w[j];
        #pragma unroll
        for (int e = 0; e < Ed; e++) sm[GSM + t * 17 + e] = row[e];
    }
    __syncthreads();

    // --- 16-warp decomposition: warp = (mh, nq); 16 rows x 16 cols each ---
    const int lane = t & 31, warp = t >> 5;
    const int gid = lane >> 2, tig = lane & 3;
    const int mh = warp & 1, nq = warp >> 1;          // nq in 0..7
    const int row0 = mh * 16 + gid, row1 = row0 + 8;
    const int sw0 = swz(row0), sw1 = swz(row1);
    const int nl = t & 127, kg = t >> 7;              // staging: kg in 0..3
    const int snl = swz(nl);

    float yfrag[4][2][4];
    #pragma unroll
    for (int a = 0; a < 4; a++)
        #pragma unroll
        for (int b = 0; b < 2; b++)
            #pragma unroll
            for (int c = 0; c < 4; c++) yfrag[a][b][c] = 0.f;

    for (int e = 0; e < Ed; e++){
        const float* W1e = W1 + (size_t)e * Dd * Hd;
        const float* W2e = W2 + (size_t)e * Hd * Od;
        const float g0 = sm[GSM + row0 * 17 + e];
        const float g1 = sm[GSM + row1 * 17 + e];

        for (int hc = 0; hc < Hd / 128; hc++){
            // ---------------- GEMM1: h-chunk [32 x 128] over K=512 ----------
            float hf[2][4];
            #pragma unroll
            for (int a = 0; a < 2; a++)
                #pragma unroll
                for (int c = 0; c < 4; c++) hf[a][c] = 0.f;

            for (int kt = 0; kt < 8; kt++){
                __syncthreads();
                {   // stage W1 panel transposed: W1P[n][k'] (k local 0..63)
                    const float* src = W1e + (size_t)(kt*64 + kg*16) * Hd + hc*128 + nl;
                    float* dst = &sm[W1P + nl * W1P_S];
                    #pragma unroll 8
                    for (int i = 0; i < 16; i++)
                        dst[pkm(kg*16 + i) ^ snl] = rna(src[(size_t)i * Hd]);
                }
                __syncthreads();
                #pragma unroll
                for (int ks = 0; ks < 8; ks++){
                    const int k0 = kt*64 + ks*8;
                    float2 aA = *(const float2*)&sm[XS + row0*XS_S + ((k0 + 2*tig) ^ sw0)];
                    float2 aB = *(const float2*)&sm[XS + row1*XS_S + ((k0 + 2*tig) ^ sw1)];
                    uint32_t a0 = __float_as_uint(aA.x), a1 = __float_as_uint(aB.x);
                    uint32_t a2 = __float_as_uint(aA.y), a3 = __float_as_uint(aB.y);
                    const int kl = ks*8 + 2*tig;
                    #pragma unroll
                    for (int nt = 0; nt < 2; nt++){
                        int n = nq*16 + nt*8 + gid;
                        float2 bb = *(const float2*)&sm[W1P + n*W1P_S + (kl ^ swz(n))];
                        mma_tf32(hf[nt], a0, a1, a2, a3,
                                 __float_as_uint(bb.x), __float_as_uint(bb.y));
                    }
                }
            }
            // store h chunk: gate * relu(h + b1), tf32-rounded (perm+swizzle)
            #pragma unroll
            for (int nt = 0; nt < 2; nt++){
                int j0 = nq*16 + nt*8 + 2*tig;                   // local col, even
                float bv0 = b1[(size_t)e * Hd + hc*128 + j0];
                float bv1 = b1[(size_t)e * Hd + hc*128 + j0 + 1];
                sm[HCH + row0*HCH_S + (pkm(j0)     ^ sw0)] = rna(g0 * fmaxf(hf[nt][0] + bv0, 0.f));
                sm[HCH + row0*HCH_S + (pkm(j0 + 1) ^ sw0)] = rna(g0 * fmaxf(hf[nt][1] + bv1, 0.f));
                sm[HCH + row1*HCH_S + (pkm(j0)     ^ sw1)] = rna(g1 * fmaxf(hf[nt][2] + bv0, 0.f));
                sm[HCH + row1*HCH_S + (pkm(j0 + 1) ^ sw1)] = rna(g1 * fmaxf(hf[nt][3] + bv1, 0.f));
            }

            // ---------------- GEMM2: y += hchunk @ W2[hc rows] --------------
            #pragma unroll 1
            for (int nc = 0; nc < 4; nc++){
                __syncthreads();
                {   // stage W2 panel transposed: W2P[n][k'] (k local 0..127)
                    const float* src = W2e + (size_t)(hc*128 + kg*32) * Od + nc*128 + nl;
                    float* dst = &sm[W2P + nl * W2P_S];
                    #pragma unroll 8
                    for (int i = 0; i < 32; i++)
                        dst[pkm(kg*32 + i) ^ snl] = rna(src[(size_t)i * Od]);
                }
                __syncthreads();
                #pragma unroll
                for (int ks = 0; ks < 16; ks++){
                    const int kl = ks*8 + 2*tig;
                    float2 aA = *(const float2*)&sm[HCH + row0*HCH_S + (kl ^ sw0)];
                    float2 aB = *(const float2*)&sm[HCH + row1*HCH_S + (kl ^ sw1)];
                    uint32_t a0 = __float_as_uint(aA.x), a1 = __float_as_uint(aB.x);
                    uint32_t a2 = __float_as_uint(aA.y), a3 = __float_as_uint(aB.y);
                    #pragma unroll
                    for (int nt = 0; nt < 2; nt++){
                        int n = nq*16 + nt*8 + gid;
                        float2 bb = *(const float2*)&sm[W2P + n*W2P_S + (kl ^ swz(n))];
                        mma_tf32(yfrag[nc][nt], a0, a1, a2, a3,
                                 __float_as_uint(bb.x), __float_as_uint(bb.y));
                    }
                }
            }
        }
    }

    // --- epilogue: y + gate-weighted b2 ---
    #pragma unroll
    for (int nc = 0; nc < 4; nc++){
        #pragma unroll
        for (int nt = 0; nt < 2; nt++){
            int col = nc*128 + nq*16 + nt*8 + 2*tig;
            float s00 = 0.f, s01 = 0.f, s10 = 0.f, s11 = 0.f;
            #pragma unroll
            for (int e = 0; e < Ed; e++){
                float be0 = b2[(size_t)e * Od + col];
                float be1 = b2[(size_t)e * Od + col + 1];
                float ga = sm[GSM + row0 * 17 + e];
                float gb = sm[GSM + row1 * 17 + e];
                s00 = fmaf(ga, be0, s00); s01 = fmaf(ga, be1, s01);
                s10 = fmaf(gb, be0, s10); s11 = fmaf(gb, be1, s11);
            }
            *(float2*)&out[(size_t)(m0 + row0) * Od + col] =
                make_float2(yfrag[nc][nt][0] + s00, yfrag[nc][nt][1] + s01);
            *(float2*)&out[(size_t)(m0 + row1) * Od + col] =
                make_float2(yfrag[nc][nt][2] + s10, yfrag[nc][nt][3] + s11);
        }
    }
}

// ======================= independent loss kernel (round-9 verbatim) ========
__global__ __launch_bounds__(256, 1)
void loss_kernel(const float* __restrict__ x, const float* __restrict__ query,
                 const float* __restrict__ c8a, const float* __restrict__ c8b,
                 const float* __restrict__ tg, float* __restrict__ out, int out_size)
{
    __shared__ float red[256]; __shared__ int redi[256];
    __shared__ int s_nz[8]; __shared__ int s_zeroA;
    __shared__ float s_imp[Ed], s_cnt[Ed];
    const int t = threadIdx.x;
    {
        int nz = 0;
        for (int i = t; i < Dd * Ed; i += 256) nz |= (__float_as_uint(c8a[i]) != 0u);
        #pragma unroll
        for (int s = 16; s; s >>= 1) nz |= __shfl_xor_sync(0xffffffffu, nz, s);
        if ((t & 31) == 0) s_nz[t >> 5] = nz;
        __syncthreads();
        if (t == 0){
            int v = 0;
            #pragma unroll
            for (int wp = 0; wp < 8; wp++) v |= s_nz[wp];
            s_zeroA = !v;
        }
        __syncthreads();
    }
    const float* wg = s_zeroA ? c8b : c8a;

    float imp[Ed]; int cnt[Ed];
    #pragma unroll
    for (int e = 0; e < Ed; e++){ imp[e] = 0.f; cnt[e] = 0; }

    for (int bb = t; bb < B_; bb += 256){
        const float* xr = x + (size_t)bb * Dd;
        const float* qr = query + (size_t)bb * Qd;
        float lg[Ed];
        #pragma unroll
        for (int e = 0; e < Ed; e++) lg[e] = 0.f;
        for (int d = 0; d < Dd; d++){
            float xv = xr[d];
            const float4* w4 = (const float4*)(wg + (size_t)d * Ed);
            float4 w0 = w4[0], w1 = w4[1], w2 = w4[2], w3 = w4[3];
            lg[0]  = fmaf(xv, w0.x, lg[0]);  lg[1]  = fmaf(xv, w0.y, lg[1]);
            lg[2]  = fmaf(xv, w0.z, lg[2]);  lg[3]  = fmaf(xv, w0.w, lg[3]);
            lg[4]  = fmaf(xv, w1.x, lg[4]);  lg[5]  = fmaf(xv, w1.y, lg[5]);
            lg[6]  = fmaf(xv, w1.z, lg[6]);  lg[7]  = fmaf(xv, w1.w, lg[7]);
            lg[8]  = fmaf(xv, w2.x, lg[8]);  lg[9]  = fmaf(xv, w2.y, lg[9]);
            lg[10] = fmaf(xv, w2.z, lg[10]); lg[11] = fmaf(xv, w2.w, lg[11]);
            lg[12] = fmaf(xv, w3.x, lg[12]); lg[13] = fmaf(xv, w3.y, lg[13]);
            lg[14] = fmaf(xv, w3.z, lg[14]); lg[15] = fmaf(xv, w3.w, lg[15]);
        }
        for (int qd = 0; qd < Qd; qd++){
            float qv = qr[qd];
            const float4* w4 = (const float4*)(tg + (size_t)qd * Ed);
            float4 w0 = w4[0], w1 = w4[1], w2 = w4[2], w3 = w4[3];
            lg[0]  = fmaf(qv, w0.x, lg[0]);  lg[1]  = fmaf(qv, w0.y, lg[1]);
            lg[2]  = fmaf(qv, w0.z, lg[2]);  lg[3]  = fmaf(qv, w0.w, lg[3]);
            lg[4]  = fmaf(qv, w1.x, lg[4]);  lg[5]  = fmaf(qv, w1.y, lg[5]);
            lg[6]  = fmaf(qv, w1.z, lg[6]);  lg[7]  = fmaf(qv, w1.w, lg[7]);
            lg[8]  = fmaf(qv, w2.x, lg[8]);  lg[9]  = fmaf(qv, w2.y, lg[9]);
            lg[10] = fmaf(qv, w2.z, lg[10]); lg[11] = fmaf(qv, w2.w, lg[11]);
            lg[12] = fmaf(qv, w3.x, lg[12]); lg[13] = fmaf(qv, w3.y, lg[13]);
            lg[14] = fmaf(qv, w3.z, lg[14]); lg[15] = fmaf(qv, w3.w, lg[15]);
        }
        int idx[Kk]; float w[Kk];
        top4_softmax(lg, idx, w);
        #pragma unroll
        for (int j = 0; j < Kk; j++){ imp[idx[j]] += w[j]; cnt[idx[j]]++; }
    }

    for (int e = 0; e < Ed; e++){
        red[t] = imp[e]; redi[t] = cnt[e]; __syncthreads();
        for (int s = 128; s; s >>= 1){
            if (t < s){ red[t] += red[t + s]; redi[t] += redi[t + s]; }
            __syncthreads();
        }
        if (t == 0){ s_imp[e] = red[0]; s_cnt[e] = (float)redi[0]; }
        __syncthreads();
    }
    if (t == 0){
        float mi = 0.f, ml = 0.f;
        #pragma unroll
        for (int e = 0; e < Ed; e++){ mi += s_imp[e]; ml += s_cnt[e]; }
        mi *= (1.f / Ed); ml *= (1.f / Ed);
        float vi = 0.f, vl = 0.f;
        #pragma unroll
        for (int e = 0; e < Ed; e++){
            float di = s_imp[e] - mi; vi += di * di;
            float dl = s_cnt[e] - ml; vl += dl * dl;
        }
        vi *= (1.f / (Ed - 1)); vl *= (1.f / (Ed - 1));
        float L = 0.01f * (vi / (mi * mi + 1e-10f) + vl / (ml * ml + 1e-10f));
        for (int i = B_ * Od; i < out_size; i++) out[i] = L;
    }
}

// ---------------- launch ----------------
extern "C" void kernel_launch(void* const* d_in, const int* in_sizes, int n_in,
                              void* d_out, int out_size)
{
    // Bind inputs by element count (validated in rounds 9/10).
    int iq = -1, ix = -1, itg = -1, ib1 = -1, iW1 = -1, iW2 = -1, i81 = -1, i82 = -1;
    for (int i = 0; i < n_in; i++){
        switch (in_sizes[i]){
            case 1048576: if (iq  < 0) iq  = i; break;
            case 2097152: if (ix  < 0) ix  = i; break;
            case 4096:    if (itg < 0) itg = i; break;
            case 16384:   if (ib1 < 0) ib1 = i; break;
            case 8192:    if (i81 < 0) i81 = i; else if (i82 < 0) i82 = i; break;
            case 8388608: if (iW1 < 0) iW1 = i; else if (iW2 < 0) iW2 = i; break;
            default: break;   // k scalar etc: ignore
        }
    }
    if (iq < 0 || ix < 0 || itg < 0 || ib1 < 0 ||
        iW1 < 0 || iW2 < 0 || i81 < 0 || i82 < 0){
        iq = 0; ix = 1; i81 = 2; itg = 3; iW1 = 4; ib1 = 5; iW2 = 6; i82 = 7;
    }
    const float* query = (const float*)d_in[iq];
    const float* x     = (const float*)d_in[ix];
    const float* c8a   = (const float*)d_in[i81];
    const float* c8b   = (const float*)d_in[i82];
    const float* tg    = (const float*)d_in[itg];
    const float* W1    = (const float*)d_in[iW1];
    const float* b1    = (const float*)d_in[ib1];
    const float* W2    = (const float*)d_in[iW2];
    float* out = (float*)d_out;

    const int smem_bytes = SMEM_F * 4;   // 194816
    cudaFuncSetAttribute(moe_dense_mma,
                         cudaFuncAttributeMaxDynamicSharedMemorySize, smem_bytes);

    moe_dense_mma<<<B_ / TM, NT_, smem_bytes>>>(x, query, c8a, c8b, tg, W1, b1, W2, out);
    if (out_size > B_ * Od)
        loss_kernel<<<1, 256>>>(x, query, c8a, c8b, tg, out, out_size);
}

// round 13
// speedup vs baseline: 1.6478x; 1.2785x over previous
#include <cuda_runtime.h>
#include <cstdint>

// Problem dims (fixed by the dataset)
#define B_   4096
#define Qd   256
#define Dd   512
#define Hd   1024
#define Od   512
#define Ed   16
#define Kk   4
#define TM   32      // tokens per block
#define NT_  512     // 16 warps

// ---- dynamic smem layout (float offsets) ----------------------------------
// XS : x tile  [32][520]  tf32, paired-k perm + xor swizzle (A-side)
// WP : weight panel ring, 2 x [64 k][136 n] k-major (B-side, cp.async)
// HCH: h chunk [32][136]  tf32, pkm+swz (A-side of GEMM2)
#define XS     0
#define XS_S   520
#define WP     (XS + TM*XS_S)          // 16640
#define WP_S   136
#define WPBUF  (64*WP_S)               // 8704 floats per buffer
#define HCH    (WP + 2*WPBUF)          // 34048
#define HCH_S  136
#define LG     (HCH + TM*HCH_S)        // 38400
#define GSM    (LG + TM*17)            // 38944
#define SMEM_F (GSM + TM*17)           // 39488 floats = 157952 bytes

// ---- helpers --------------------------------------------------------------
__device__ __forceinline__ float rna(float x){
    uint32_t u; asm("cvt.rna.tf32.f32 %0, %1;" : "=r"(u) : "f"(x));
    return __uint_as_float(u);
}
__device__ __forceinline__ uint32_t rna_u(float x){
    uint32_t u; asm("cvt.rna.tf32.f32 %0, %1;" : "=r"(u) : "f"(x));
    return u;
}
// paired-k permutation: (j, j+4) adjacent -> one float2 per tf32 frag pair
__device__ __forceinline__ int pkm(int k){ return (k & ~7) + 2*(k & 3) + ((k >> 2) & 1); }
// xor swizzle per row (A-side layouts)
__device__ __forceinline__ int swz(int r){ return 2 * ((r >> 2) & 7); }

__device__ __forceinline__ void cp16(float* smem, const float* g){
    unsigned s = (unsigned)__cvta_generic_to_shared(smem);
    asm volatile("cp.async.cg.shared.global [%0], [%1], 16;\n" :: "r"(s), "l"(g));
}
__device__ __forceinline__ void cp_commit(){ asm volatile("cp.async.commit_group;\n" ::: "memory"); }
template<int N> __device__ __forceinline__ void cp_wait(){ asm volatile("cp.async.wait_group %0;\n" :: "n"(N) : "memory"); }

__device__ __forceinline__ void mma_tf32(float* c,
    uint32_t a0, uint32_t a1, uint32_t a2, uint32_t a3, uint32_t b0, uint32_t b1){
    asm volatile(
        "mma.sync.aligned.m16n8k8.row.col.f32.tf32.tf32.f32 "
        "{%0,%1,%2,%3}, {%4,%5,%6,%7}, {%8,%9}, {%0,%1,%2,%3};\n"
        : "+f"(c[0]), "+f"(c[1]), "+f"(c[2]), "+f"(c[3])
        : "r"(a0), "r"(a1), "r"(a2), "r"(a3), "r"(b0), "r"(b1));
}

// top-4 + softmax, ties -> lowest index (matches jax top_k)
__device__ __forceinline__ void top4_softmax(const float* v, int* idx, float* w){
    unsigned used = 0; float val[Kk];
    #pragma unroll
    for (int j = 0; j < Kk; j++){
        float best = -3.4e38f; int bi = 0;
        #pragma unroll
        for (int i = 0; i < Ed; i++)
            if (!((used >> i) & 1) && v[i] > best){ best = v[i]; bi = i; }
        used |= 1u << bi; idx[j] = bi; val[j] = best;
    }
    float m = val[0], s = 0.f;
    #pragma unroll
    for (int j = 0; j < Kk; j++){ w[j] = expf(val[j] - m); s += w[j]; }
    float inv = 1.f / s;
    #pragma unroll
    for (int j = 0; j < Kk; j++) w[j] *= inv;
}

// ======================= monolithic dense MoE (tf32 mma, pipelined) ========
__global__ __launch_bounds__(NT_, 1)
void moe_dense_mma(const float* __restrict__ x, const float* __restrict__ query,
                   const float* __restrict__ c8a, const float* __restrict__ c8b,
                   const float* __restrict__ tg,
                   const float* __restrict__ W1, const float* __restrict__ b1,
                   const float* __restrict__ W2, float* __restrict__ out)
{
    extern __shared__ float sm[];
    const int t  = threadIdx.x;
    const int m0 = blockIdx.x * TM;

    // --- resolve the 8192-element collision: b2 is the all-zero buffer ---
    __shared__ int s_nz[16]; __shared__ int s_zeroA;
    {
        int nz = 0;
        for (int i = t; i < Dd * Ed; i += NT_) nz |= (__float_as_uint(c8a[i]) != 0u);
        #pragma unroll
        for (int s = 16; s; s >>= 1) nz |= __shfl_xor_sync(0xffffffffu, nz, s);
        if ((t & 31) == 0) s_nz[t >> 5] = nz;
        __syncthreads();
        if (t == 0){
            int v = 0;
            #pragma unroll
            for (int wp = 0; wp < 16; wp++) v |= s_nz[wp];
            s_zeroA = !v;
        }
        __syncthreads();
    }
    const float* wg = s_zeroA ? c8b : c8a;
    const float* b2 = s_zeroA ? c8a : c8b;

    // --- stage x tile: tf32-rounded, perm+swizzled ---
    for (int p = 0; p < 32; p++){
        int idx = p * NT_ + t;             // 0..16383
        int row = idx >> 9, col = idx & 511;
        sm[XS + row * XS_S + (pkm(col) ^ swz(row))] =
            rna(x[(size_t)(m0 + row) * Dd + col]);
    }

    // --- gating on EXACT fp32 x: one (tok, e) logit per thread ---
    {
        int tok = t >> 4, e = t & 15;      // 512 threads = 32 x 16
        const float* xr = x + (size_t)(m0 + tok) * Dd;
        float s = 0.f;
        for (int d = 0; d < Dd; d++)  s = fmaf(xr[d], wg[d * Ed + e], s);
        const float* qr = query + (size_t)(m0 + tok) * Qd;
        for (int qd = 0; qd < Qd; qd++) s = fmaf(qr[qd], tg[qd * Ed + e], s);
        sm[LG + tok * 17 + e] = s;
    }
    __syncthreads();
    if (t < TM){
        float v[Ed];
        #pragma unroll
        for (int e = 0; e < Ed; e++) v[e] = sm[LG + t * 17 + e];
        int idx[Kk]; float w[Kk];
        top4_softmax(v, idx, w);
        float row[Ed];
        #pragma unroll
        for (int e = 0; e < Ed; e++) row[e] = 0.f;
        #pragma unroll
        for (int j = 0; j < Kk; j++) row[idx[j]] = w[j];
        #pragma unroll
        for (int e = 0; e < Ed; e++) sm[GSM + t * 17 + e] = row[e];
    }
    __syncthreads();

    // --- 16-warp decomposition: warp = (mh, nq); 16 rows x 16 cols ---
    const int lane = t & 31, warp = t >> 5;
    const int gid = lane >> 2, tig = lane & 3;
    const int mh = warp & 1, nq = warp >> 1;          // nq in 0..7
    const int row0 = mh * 16 + gid, row1 = row0 + 8;
    const int sw0 = swz(row0), sw1 = swz(row1);

    // staging thread map: 2048 float4 per stage, 4 per thread
    const int skr0 = (t * 4) >> 7;     // unused helper (kept simple below)

    // weight-panel stage issue: [64 k][128 n] k-major from gmem, cp.async
    auto issue = [&](const float* src, size_t rstride, int buf){
        float* dst = &sm[WP + buf * WPBUF];
        #pragma unroll
        for (int p = 0; p < 4; p++){
            int idx = p * NT_ + t;         // 0..2047 float4 chunks
            int kr = idx >> 5, c4 = idx & 31;
            cp16(&dst[kr * WP_S + c4 * 4], src + (size_t)kr * rstride + c4 * 4);
        }
        cp_commit();
    };

    float yfrag[4][2][4];
    #pragma unroll
    for (int a = 0; a < 4; a++)
        #pragma unroll
        for (int b = 0; b < 2; b++)
            #pragma unroll
            for (int c = 0; c < 4; c++) yfrag[a][b][c] = 0.f;

    for (int e = 0; e < Ed; e++){
        const float* W1e = W1 + (size_t)e * Dd * Hd;
        const float* W2e = W2 + (size_t)e * Hd * Od;
        const float g0 = sm[GSM + row0 * 17 + e];
        const float g1 = sm[GSM + row1 * 17 + e];

        for (int hc = 0; hc < Hd / 128; hc++){
            // ============ GEMM1: h-chunk [32 x 128], K=512, 8 stages =======
            float hf[2][4];
            #pragma unroll
            for (int a = 0; a < 2; a++)
                #pragma unroll
                for (int c = 0; c < 4; c++) hf[a][c] = 0.f;

            issue(W1e + 0 * Hd + hc * 128, Hd, 0);
            for (int kt = 0; kt < 8; kt++){
                if (kt + 1 < 8) { issue(W1e + (size_t)((kt+1)*64) * Hd + hc*128, Hd, (kt+1) & 1); cp_wait<1>(); }
                else            cp_wait<0>();
                __syncthreads();
                const float* wpB = &sm[WP + (kt & 1) * WPBUF];
                #pragma unroll
                for (int ks = 0; ks < 8; ks++){
                    const int kgl = kt*64 + ks*8;                // global k
                    float2 aA = *(const float2*)&sm[XS + row0*XS_S + ((kgl + 2*tig) ^ sw0)];
                    float2 aB = *(const float2*)&sm[XS + row1*XS_S + ((kgl + 2*tig) ^ sw1)];
                    uint32_t a0 = __float_as_uint(aA.x), a1 = __float_as_uint(aB.x);
                    uint32_t a2 = __float_as_uint(aA.y), a3 = __float_as_uint(aB.y);
                    const float* bp = wpB + (ks*8 + tig) * WP_S + nq*16 + gid;
                    #pragma unroll
                    for (int nt = 0; nt < 2; nt++){
                        float b0 = bp[nt*8], b1 = bp[nt*8 + 4*WP_S];
                        mma_tf32(hf[nt], a0, a1, a2, a3, rna_u(b0), rna_u(b1));
                    }
                }
                __syncthreads();
            }
            // store h chunk: gate * relu(h + b1), tf32, pkm+swz
            #pragma unroll
            for (int nt = 0; nt < 2; nt++){
                int j0 = nq*16 + nt*8 + 2*tig;                   // local col, even
                float bv0 = b1[(size_t)e * Hd + hc*128 + j0];
                float bv1 = b1[(size_t)e * Hd + hc*128 + j0 + 1];
                sm[HCH + row0*HCH_S + (pkm(j0)     ^ sw0)] = rna(g0 * fmaxf(hf[nt][0] + bv0, 0.f));
                sm[HCH + row0*HCH_S + (pkm(j0 + 1) ^ sw0)] = rna(g0 * fmaxf(hf[nt][1] + bv1, 0.f));
                sm[HCH + row1*HCH_S + (pkm(j0)     ^ sw1)] = rna(g1 * fmaxf(hf[nt][2] + bv0, 0.f));
                sm[HCH + row1*HCH_S + (pkm(j0 + 1) ^ sw1)] = rna(g1 * fmaxf(hf[nt][3] + bv1, 0.f));
            }
            __syncthreads();   // HCH visible to all before GEMM2 reads

            // ============ GEMM2: y += hchunk @ W2, 8 stages (kt x nc) ======
            issue(W2e + (size_t)(hc*128) * Od + 0, Od, 0);
            for (int s = 0; s < 8; s++){
                const int kt = s >> 2, nc = s & 3;
                if (s + 1 < 8){
                    const int kt1 = (s+1) >> 2, nc1 = (s+1) & 3;
                    issue(W2e + (size_t)(hc*128 + kt1*64) * Od + nc1*128, Od, (s+1) & 1);
                    cp_wait<1>();
                } else cp_wait<0>();
                __syncthreads();
                const float* wpB = &sm[WP + (s & 1) * WPBUF];
                #pragma unroll
                for (int ks = 0; ks < 8; ks++){
                    const int kl = kt*64 + ks*8;                 // local k in h
                    float2 aA = *(const float2*)&sm[HCH + row0*HCH_S + ((kl + 2*tig) ^ sw0)];
                    float2 aB = *(const float2*)&sm[HCH + row1*HCH_S + ((kl + 2*tig) ^ sw1)];
                    uint32_t a0 = __float_as_uint(aA.x), a1 = __float_as_uint(aB.x);
                    uint32_t a2 = __float_as_uint(aA.y), a3 = __float_as_uint(aB.y);
                    const float* bp = wpB + (ks*8 + tig) * WP_S + nq*16 + gid;
                    #pragma unroll
                    for (int nt = 0; nt < 2; nt++){
                        float b0 = bp[nt*8], b1 = bp[nt*8 + 4*WP_S];
                        mma_tf32(yfrag[nc][nt], a0, a1, a2, a3, rna_u(b0), rna_u(b1));
                    }
                }
                __syncthreads();
            }
        }
    }

    // --- epilogue: y + gate-weighted b2 ---
    #pragma unroll
    for (int nc = 0; nc < 4; nc++){
        #pragma unroll
        for (int nt = 0; nt < 2; nt++){
            int col = nc*128 + nq*16 + nt*8 + 2*tig;
            float s00 = 0.f, s01 = 0.f, s10 = 0.f, s11 = 0.f;
            #pragma unroll
            for (int e = 0; e < Ed; e++){
                float be0 = b2[(size_t)e * Od + col];
                float be1 = b2[(size_t)e * Od + col + 1];
                float ga = sm[GSM + row0 * 17 + e];
                float gb = sm[GSM + row1 * 17 + e];
                s00 = fmaf(ga, be0, s00); s01 = fmaf(ga, be1, s01);
                s10 = fmaf(gb, be0, s10); s11 = fmaf(gb, be1, s11);
            }
            *(float2*)&out[(size_t)(m0 + row0) * Od + col] =
                make_float2(yfrag[nc][nt][0] + s00, yfrag[nc][nt][1] + s01);
            *(float2*)&out[(size_t)(m0 + row1) * Od + col] =
                make_float2(yfrag[nc][nt][2] + s10, yfrag[nc][nt][3] + s11);
        }
    }
}

// ======================= independent loss kernel (verbatim) ================
__global__ __launch_bounds__(256, 1)
void loss_kernel(const float* __restrict__ x, const float* __restrict__ query,
                 const float* __restrict__ c8a, const float* __restrict__ c8b,
                 const float* __restrict__ tg, float* __restrict__ out, int out_size)
{
    __shared__ float red[256]; __shared__ int redi[256];
    __shared__ int s_nz[8]; __shared__ int s_zeroA;
    __shared__ float s_imp[Ed], s_cnt[Ed];
    const int t = threadIdx.x;
    {
        int nz = 0;
        for (int i = t; i < Dd * Ed; i += 256) nz |= (__float_as_uint(c8a[i]) != 0u);
        #pragma unroll
        for (int s = 16; s; s >>= 1) nz |= __shfl_xor_sync(0xffffffffu, nz, s);
        if ((t & 31) == 0) s_nz[t >> 5] = nz;
        __syncthreads();
        if (t == 0){
            int v = 0;
            #pragma unroll
            for (int wp = 0; wp < 8; wp++) v |= s_nz[wp];
            s_zeroA = !v;
        }
        __syncthreads();
    }
    const float* wg = s_zeroA ? c8b : c8a;

    float imp[Ed]; int cnt[Ed];
    #pragma unroll
    for (int e = 0; e < Ed; e++){ imp[e] = 0.f; cnt[e] = 0; }

    for (int bb = t; bb < B_; bb += 256){
        const float* xr = x + (size_t)bb * Dd;
        const float* qr = query + (size_t)bb * Qd;
        float lg[Ed];
        #pragma unroll
        for (int e = 0; e < Ed; e++) lg[e] = 0.f;
        for (int d = 0; d < Dd; d++){
            float xv = xr[d];
            const float4* w4 = (const float4*)(wg + (size_t)d * Ed);
            float4 w0 = w4[0], w1 = w4[1], w2 = w4[2], w3 = w4[3];
            lg[0]  = fmaf(xv, w0.x, lg[0]);  lg[1]  = fmaf(xv, w0.y, lg[1]);
            lg[2]  = fmaf(xv, w0.z, lg[2]);  lg[3]  = fmaf(xv, w0.w, lg[3]);
            lg[4]  = fmaf(xv, w1.x, lg[4]);  lg[5]  = fmaf(xv, w1.y, lg[5]);
            lg[6]  = fmaf(xv, w1.z, lg[6]);  lg[7]  = fmaf(xv, w1.w, lg[7]);
            lg[8]  = fmaf(xv, w2.x, lg[8]);  lg[9]  = fmaf(xv, w2.y, lg[9]);
            lg[10] = fmaf(xv, w2.z, lg[10]); lg[11] = fmaf(xv, w2.w, lg[11]);
            lg[12] = fmaf(xv, w3.x, lg[12]); lg[13] = fmaf(xv, w3.y, lg[13]);
            lg[14] = fmaf(xv, w3.z, lg[14]); lg[15] = fmaf(xv, w3.w, lg[15]);
        }
        for (int qd = 0; qd < Qd; qd++){
            float qv = qr[qd];
            const float4* w4 = (const float4*)(tg + (size_t)qd * Ed);
            float4 w0 = w4[0], w1 = w4[1], w2 = w4[2], w3 = w4[3];
            lg[0]  = fmaf(qv, w0.x, lg[0]);  lg[1]  = fmaf(qv, w0.y, lg[1]);
            lg[2]  = fmaf(qv, w0.z, lg[2]);  lg[3]  = fmaf(qv, w0.w, lg[3]);
            lg[4]  = fmaf(qv, w1.x, lg[4]);  lg[5]  = fmaf(qv, w1.y, lg[5]);
            lg[6]  = fmaf(qv, w1.z, lg[6]);  lg[7]  = fmaf(qv, w1.w, lg[7]);
            lg[8]  = fmaf(qv, w2.x, lg[8]);  lg[9]  = fmaf(qv, w2.y, lg[9]);
            lg[10] = fmaf(qv, w2.z, lg[10]); lg[11] = fmaf(qv, w2.w, lg[11]);
            lg[12] = fmaf(qv, w3.x, lg[12]); lg[13] = fmaf(qv, w3.y, lg[13]);
            lg[14] = fmaf(qv, w3.z, lg[14]); lg[15] = fmaf(qv, w3.w, lg[15]);
        }
        int idx[Kk]; float w[Kk];
        top4_softmax(lg, idx, w);
        #pragma unroll
        for (int j = 0; j < Kk; j++){ imp[idx[j]] += w[j]; cnt[idx[j]]++; }
    }

    for (int e = 0; e < Ed; e++){
        red[t] = imp[e]; redi[t] = cnt[e]; __syncthreads();
        for (int s = 128; s; s >>= 1){
            if (t < s){ red[t] += red[t + s]; redi[t] += redi[t + s]; }
            __syncthreads();
        }
        if (t == 0){ s_imp[e] = red[0]; s_cnt[e] = (float)redi[0]; }
        __syncthreads();
    }
    if (t == 0){
        float mi = 0.f, ml = 0.f;
        #pragma unroll
        for (int e = 0; e < Ed; e++){ mi += s_imp[e]; ml += s_cnt[e]; }
        mi *= (1.f / Ed); ml *= (1.f / Ed);
        float vi = 0.f, vl = 0.f;
        #pragma unroll
        for (int e = 0; e < Ed; e++){
            float di = s_imp[e] - mi; vi += di * di;
            float dl = s_cnt[e] - ml; vl += dl * dl;
        }
        vi *= (1.f / (Ed - 1)); vl *= (1.f / (Ed - 1));
        float L = 0.01f * (vi / (mi * mi + 1e-10f) + vl / (ml * ml + 1e-10f));
        for (int i = B_ * Od; i < out_size; i++) out[i] = L;
    }
}

// ---------------- launch ----------------
extern "C" void kernel_launch(void* const* d_in, const int* in_sizes, int n_in,
                              void* d_out, int out_size)
{
    // Bind inputs by element count (validated rounds 9-11).
    int iq = -1, ix = -1, itg = -1, ib1 = -1, iW1 = -1, iW2 = -1, i81 = -1, i82 = -1;
    for (int i = 0; i < n_in; i++){
        switch (in_sizes[i]){
            case 1048576: if (iq  < 0) iq  = i; break;
            case 2097152: if (ix  < 0) ix  = i; break;
            case 4096:    if (itg < 0) itg = i; break;
            case 16384:   if (ib1 < 0) ib1 = i; break;
            case 8192:    if (i81 < 0) i81 = i; else if (i82 < 0) i82 = i; break;
            case 8388608: if (iW1 < 0) iW1 = i; else if (iW2 < 0) iW2 = i; break;
            default: break;   // k scalar etc: ignore
        }
    }
    if (iq < 0 || ix < 0 || itg < 0 || ib1 < 0 ||
        iW1 < 0 || iW2 < 0 || i81 < 0 || i82 < 0){
        iq = 0; ix = 1; i81 = 2; itg = 3; iW1 = 4; ib1 = 5; iW2 = 6; i82 = 7;
    }
    const float* query = (const float*)d_in[iq];
    const float* x     = (const float*)d_in[ix];
    const float* c8a   = (const float*)d_in[i81];
    const float* c8b   = (const float*)d_in[i82];
    const float* tg    = (const float*)d_in[itg];
    const float* W1    = (const float*)d_in[iW1];
    const float* b1    = (const float*)d_in[ib1];
    const float* W2    = (const float*)d_in[iW2];
    float* out = (float*)d_out;

    const int smem_bytes = SMEM_F * 4;   // 157952
    cudaFuncSetAttribute(moe_dense_mma,
                         cudaFuncAttributeMaxDynamicSharedMemorySize, smem_bytes);

    moe_dense_mma<<<B_ / TM, NT_, smem_bytes>>>(x, query, c8a, c8b, tg, W1, b1, W2, out);
    if (out_size > B_ * Od)
        loss_kernel<<<1, 256>>>(x, query, c8a, c8b, tg, out, out_size);
}